// round 2
// baseline (speedup 1.0000x reference)
#include <cuda_runtime.h>

#define WIN   3072
#define HOP   192
#define NB    8
#define NT    1000
#define NF    128
#define NOISE_LEN ((NT-1)*HOP)   /* 191808 */
#define HALF  (WIN/2)            /* 1536 */
#define NTHREADS 256

#define PHY(i) ((i) + ((i)>>5))
#define SBUF (WIN + (WIN>>5))    /* 3168 */

__device__ float2 g_tw[WIN];      // w3072^j = exp(-2*pi*i*j/3072)
__device__ float  g_hann[WIN];
__device__ float  g_scratch[NB*NT*WIN];   // windowed out_frames, ~98 MB

// ---------------------------------------------------------------- complex ops
__device__ __forceinline__ float2 cadd(float2 a, float2 b){ return make_float2(a.x+b.x, a.y+b.y); }
__device__ __forceinline__ float2 csub(float2 a, float2 b){ return make_float2(a.x-b.x, a.y-b.y); }
__device__ __forceinline__ float2 cmul(float2 a, float2 b){
    return make_float2(a.x*b.x - a.y*b.y, a.x*b.y + a.y*b.x);
}

// forward DFT-4 (e^{-2pi i jk/4}); outputs written back in k order
__device__ __forceinline__ void dft4(float2 &a0, float2 &a1, float2 &a2, float2 &a3){
    float2 t0 = cadd(a0,a2), t1 = csub(a0,a2);
    float2 t2 = cadd(a1,a3), t3 = csub(a1,a3);
    a0 = cadd(t0,t2);
    a2 = csub(t0,t2);
    a1 = make_float2(t1.x + t3.y, t1.y - t3.x);  // t1 - i*t3
    a3 = make_float2(t1.x - t3.y, t1.y + t3.x);  // t1 + i*t3
}

// forward DFT-3
__device__ __forceinline__ void dft3(float2 &a, float2 &b, float2 &c){
    float2 s = cadd(b,c);
    float2 d = csub(b,c);
    float2 t = make_float2(a.x - 0.5f*s.x, a.y - 0.5f*s.y);
    float ux = 0.8660254037844386f*d.x, uy = 0.8660254037844386f*d.y;
    float2 y0 = cadd(a,s);
    b = make_float2(t.x + uy, t.y - ux);  // t - i*u
    c = make_float2(t.x - uy, t.y + ux);  // t + i*u
    a = y0;
}

// DFT-12, input v[j] with j = r + 4c (r in 0..3, c in 0..2).
// After: X[k3 + 3*k1] sits at v[k1 + 4*k3].
__device__ __forceinline__ void dft12(float2 *v){
    dft3(v[0], v[4], v[8]);
    dft3(v[1], v[5], v[9]);
    dft3(v[2], v[6], v[10]);
    dft3(v[3], v[7], v[11]);
    const float H3 = 0.8660254037844386f;
    // twiddle w12^{r*k3} applied to v[r + 4*k3]
    v[5]  = cmul(v[5],  make_float2( H3,  -0.5f));   // w12^1
    v[6]  = cmul(v[6],  make_float2( 0.5f, -H3));    // w12^2
    v[7]  = make_float2(v[7].y, -v[7].x);            // w12^3 = -i
    v[9]  = cmul(v[9],  make_float2( 0.5f, -H3));    // w12^2
    v[10] = cmul(v[10], make_float2(-0.5f, -H3));    // w12^4
    v[11] = make_float2(-v[11].x, -v[11].y);         // w12^6 = -1
    dft4(v[0], v[1], v[2],  v[3]);
    dft4(v[4], v[5], v[6],  v[7]);
    dft4(v[8], v[9], v[10], v[11]);
}

// DFT-16, input v[j] with j = r + 4c (r,c in 0..3).
// After: X[k4 + 4*k1] sits at v[k1 + 4*k4].
__device__ __forceinline__ void dft16(float2 *v){
    dft4(v[0], v[4], v[8],  v[12]);
    dft4(v[1], v[5], v[9],  v[13]);
    dft4(v[2], v[6], v[10], v[14]);
    dft4(v[3], v[7], v[11], v[15]);
    const float C1 = 0.9238795325112867f;
    const float S1 = 0.3826834323650898f;
    const float R2 = 0.7071067811865476f;
    // twiddle w16^{r*k4} applied to v[r + 4*k4]
    v[5]  = cmul(v[5],  make_float2( C1, -S1));   // w16^1
    v[6]  = cmul(v[6],  make_float2( R2, -R2));   // w16^2
    v[7]  = cmul(v[7],  make_float2( S1, -C1));   // w16^3
    v[9]  = cmul(v[9],  make_float2( R2, -R2));   // w16^2
    v[10] = make_float2(v[10].y, -v[10].x);       // w16^4 = -i
    v[11] = cmul(v[11], make_float2(-R2, -R2));   // w16^6
    v[13] = cmul(v[13], make_float2( S1, -C1));   // w16^3
    v[14] = cmul(v[14], make_float2(-R2, -R2));   // w16^6
    v[15] = cmul(v[15], make_float2(-C1,  S1));   // w16^9
    dft4(v[0], v[1], v[2],  v[3]);
    dft4(v[4], v[5], v[6],  v[7]);
    dft4(v[8], v[9], v[10], v[11]);
    dft4(v[12],v[13],v[14], v[15]);
}

// In-place (register-staged) 3072-point complex FFT over shared RE/IM.
// Stages: radix-12 (n=3072,s=1,m=256), radix-16 (n=256,s=12,m=16),
//         radix-16 (n=16,s=192,m=1). Natural-order output.
__device__ void fft3072(float *RE, float *IM, int tid){
    float2 v[16];

    // ---- stage 1: radix-12, 256 butterflies, one per thread
    {
        int p = tid;
        #pragma unroll
        for (int i = 0; i < 12; i++){
            int idx = PHY(p + 256*i);
            v[i] = make_float2(RE[idx], IM[idx]);
        }
        __syncthreads();
        dft12(v);
        #pragma unroll
        for (int k = 0; k < 12; k++){
            float2 X = v[(k/3) + 4*(k%3)];
            if (k) X = cmul(X, g_tw[p*k]);
            int idx = PHY(12*p + k);
            RE[idx] = X.x; IM[idx] = X.y;
        }
        __syncthreads();
    }

    // ---- stage 2: radix-16, s=12, 192 butterflies (tid = 12*p + q)
    {
        bool act = tid < 192;
        int q = tid % 12, p = tid / 12;
        if (act){
            #pragma unroll
            for (int i = 0; i < 16; i++){
                int idx = PHY(tid + 192*i);      // q + 12*(p + 16*i)
                v[i] = make_float2(RE[idx], IM[idx]);
            }
        }
        __syncthreads();
        if (act){
            dft16(v);
            #pragma unroll
            for (int k = 0; k < 16; k++){
                float2 X = v[(k>>2) + 4*(k&3)];
                if (k && p) X = cmul(X, g_tw[12*p*k]);   // w256^{pk}
                int idx = PHY(q + 192*p + 12*k);          // q + 12*(16p + k)
                RE[idx] = X.x; IM[idx] = X.y;
            }
        }
        __syncthreads();
    }

    // ---- stage 3: radix-16, s=192, 192 butterflies, no twiddle
    {
        bool act = tid < 192;
        if (act){
            #pragma unroll
            for (int i = 0; i < 16; i++){
                int idx = PHY(tid + 192*i);
                v[i] = make_float2(RE[idx], IM[idx]);
            }
        }
        __syncthreads();
        if (act){
            dft16(v);
            #pragma unroll
            for (int k = 0; k < 16; k++){
                float2 X = v[(k>>2) + 4*(k&3)];
                int idx = PHY(tid + 192*k);
                RE[idx] = X.x; IM[idx] = X.y;
            }
        }
        __syncthreads();
    }
}

// ---------------------------------------------------------------- kernels
__global__ void init_tables(){
    int j = blockIdx.x*blockDim.x + threadIdx.x;
    if (j < WIN){
        double th = -6.283185307179586476925286766559 * (double)j / (double)WIN;
        g_tw[j] = make_float2((float)cos(th), (float)sin(th));
        double ha =  6.283185307179586476925286766559 * (double)j / (double)(WIN-1);
        g_hann[j] = (float)(0.5 - 0.5*cos(ha));
    }
}

__global__ void __launch_bounds__(NTHREADS)
synth_kernel(const float* __restrict__ fb, const float* __restrict__ noise){
    __shared__ float RE[SBUF];
    __shared__ float IM[SBUF];
    __shared__ float gs[NF];

    int t = blockIdx.x;
    int b = blockIdx.y;
    int tid = threadIdx.x;

    // filter gains for this (b,t): filter_bands[b,0,f,t], stride T over f
    if (tid < NF) gs[tid] = fb[(b*NF + tid)*NT + t];

    // load frame (zero-padded noise) as complex with imag = 0
    int base = t*HOP - HALF;
    const float* nb = noise + b*NOISE_LEN;
    for (int n = tid; n < WIN; n += NTHREADS){
        int idx = base + n;
        float x = (idx >= 0 && idx < NOISE_LEN) ? nb[idx] : 0.0f;
        RE[PHY(n)] = x;
        IM[PHY(n)] = 0.0f;
    }
    __syncthreads();

    // forward FFT
    fft3072(RE, IM, tid);

    // multiply by real filter H[k] and conjugate (for ifft-via-fft)
    //   H[0]=0; H[k]=g[(k-1)/12] for 1<=k<=1536; H[k]=H[3072-k] for k>1536
    for (int k = tid; k < WIN; k += NTHREADS){
        float h;
        if (k == 0)          h = 0.0f;
        else if (k <= HALF)  h = gs[(k-1)/12];
        else                 h = gs[(WIN-1-k)/12];
        int idx = PHY(k);
        RE[idx] =  RE[idx]*h;
        IM[idx] = -IM[idx]*h;
    }
    __syncthreads();

    // second forward FFT; real part / N = irfft result
    fft3072(RE, IM, tid);

    // window and store windowed frame to scratch
    const float inv = 1.0f/(float)WIN;
    float* sc = g_scratch + (b*NT + t)*WIN;
    for (int n = tid; n < WIN; n += NTHREADS){
        sc[n] = RE[PHY(n)] * inv * g_hann[n];
    }
}

__global__ void ola_kernel(float* __restrict__ out){
    int gid = blockIdx.x*blockDim.x + threadIdx.x;
    if (gid >= NB*NOISE_LEN) return;
    int b  = gid / NOISE_LEN;
    int sp = gid - b*NOISE_LEN;
    int s  = sp + HALF;                       // position in padded timeline
    int t_hi = s / HOP; if (t_hi > NT-1) t_hi = NT-1;
    int t_lo = (s >= 2880) ? (s - 2880)/HOP : 0;   // ceil((s-3071)/192)
    const float* base = g_scratch + b*NT*WIN;
    float acc = 0.0f;
    for (int tt = t_lo; tt <= t_hi; tt++){
        acc += base[tt*WIN + (s - tt*HOP)];
    }
    out[gid] = acc;
}

// ---------------------------------------------------------------- launch
extern "C" void kernel_launch(void* const* d_in, const int* in_sizes, int n_in,
                              void* d_out, int out_size){
    const float* fb    = (const float*)d_in[0];
    const float* noise = (const float*)d_in[1];
    // defensive: detect swapped input order by element counts
    if (n_in >= 2 && in_sizes[0] == NB*NOISE_LEN && in_sizes[1] == NB*NF*NT){
        const float* tmp = fb; fb = noise; noise = tmp;
    }
    float* out = (float*)d_out;

    init_tables<<<(WIN + 255)/256, 256>>>();
    dim3 grid(NT, NB);
    synth_kernel<<<grid, NTHREADS>>>(fb, noise);
    int n_out = NB*NOISE_LEN;
    ola_kernel<<<(n_out + 255)/256, 256>>>(out);
}

// round 3
// speedup vs baseline: 1.9444x; 1.9444x over previous
#include <cuda_runtime.h>

#define WIN   3072
#define HOP   192
#define NB    8
#define NT    1000
#define NF    128
#define NOISE_LEN ((NT-1)*HOP)   /* 191808 */
#define HALF  (WIN/2)            /* 1536 */
#define NTHREADS 256

#define PHY(i) ((i) + ((i)>>5))
#define SBUF (WIN + (WIN>>5))    /* 3168 */

__device__ float2 g_tw[WIN];      // w3072^j = exp(-2*pi*i*j/3072)
__device__ float  g_hann[WIN];
__device__ float  g_scratch[NB*NT*WIN];   // windowed out_frames, ~98 MB

// ---------------------------------------------------------------- complex ops
__device__ __forceinline__ float2 cadd(float2 a, float2 b){ return make_float2(a.x+b.x, a.y+b.y); }
__device__ __forceinline__ float2 csub(float2 a, float2 b){ return make_float2(a.x-b.x, a.y-b.y); }
__device__ __forceinline__ float2 cmul(float2 a, float2 b){
    return make_float2(a.x*b.x - a.y*b.y, a.x*b.y + a.y*b.x);
}

// forward DFT-4 (e^{-2pi i jk/4})
__device__ __forceinline__ void dft4(float2 &a0, float2 &a1, float2 &a2, float2 &a3){
    float2 t0 = cadd(a0,a2), t1 = csub(a0,a2);
    float2 t2 = cadd(a1,a3), t3 = csub(a1,a3);
    a0 = cadd(t0,t2);
    a2 = csub(t0,t2);
    a1 = make_float2(t1.x + t3.y, t1.y - t3.x);  // t1 - i*t3
    a3 = make_float2(t1.x - t3.y, t1.y + t3.x);  // t1 + i*t3
}

// forward DFT-3
__device__ __forceinline__ void dft3(float2 &a, float2 &b, float2 &c){
    float2 s = cadd(b,c);
    float2 d = csub(b,c);
    float2 t = make_float2(a.x - 0.5f*s.x, a.y - 0.5f*s.y);
    float ux = 0.8660254037844386f*d.x, uy = 0.8660254037844386f*d.y;
    float2 y0 = cadd(a,s);
    b = make_float2(t.x + uy, t.y - ux);  // t - i*u
    c = make_float2(t.x - uy, t.y + ux);  // t + i*u
    a = y0;
}

// DFT-12, input v[j] with j = r + 4c. After: X[k3 + 3*k1] at v[k1 + 4*k3].
__device__ __forceinline__ void dft12(float2 *v){
    dft3(v[0], v[4], v[8]);
    dft3(v[1], v[5], v[9]);
    dft3(v[2], v[6], v[10]);
    dft3(v[3], v[7], v[11]);
    const float H3 = 0.8660254037844386f;
    v[5]  = cmul(v[5],  make_float2( H3,  -0.5f));   // w12^1
    v[6]  = cmul(v[6],  make_float2( 0.5f, -H3));    // w12^2
    v[7]  = make_float2(v[7].y, -v[7].x);            // w12^3 = -i
    v[9]  = cmul(v[9],  make_float2( 0.5f, -H3));    // w12^2
    v[10] = cmul(v[10], make_float2(-0.5f, -H3));    // w12^4
    v[11] = make_float2(-v[11].x, -v[11].y);         // w12^6 = -1
    dft4(v[0], v[1], v[2],  v[3]);
    dft4(v[4], v[5], v[6],  v[7]);
    dft4(v[8], v[9], v[10], v[11]);
}

// DFT-16, input v[j] with j = r + 4c. After: X[k4 + 4*k1] at v[k1 + 4*k4].
__device__ __forceinline__ void dft16(float2 *v){
    dft4(v[0], v[4], v[8],  v[12]);
    dft4(v[1], v[5], v[9],  v[13]);
    dft4(v[2], v[6], v[10], v[14]);
    dft4(v[3], v[7], v[11], v[15]);
    const float C1 = 0.9238795325112867f;
    const float S1 = 0.3826834323650898f;
    const float R2 = 0.7071067811865476f;
    v[5]  = cmul(v[5],  make_float2( C1, -S1));   // w16^1
    v[6]  = cmul(v[6],  make_float2( R2, -R2));   // w16^2
    v[7]  = cmul(v[7],  make_float2( S1, -C1));   // w16^3
    v[9]  = cmul(v[9],  make_float2( R2, -R2));   // w16^2
    v[10] = make_float2(v[10].y, -v[10].x);       // w16^4 = -i
    v[11] = cmul(v[11], make_float2(-R2, -R2));   // w16^6
    v[13] = cmul(v[13], make_float2( S1, -C1));   // w16^3
    v[14] = cmul(v[14], make_float2(-R2, -R2));   // w16^6
    v[15] = cmul(v[15], make_float2(-C1,  S1));   // w16^9
    dft4(v[0], v[1], v[2],  v[3]);
    dft4(v[4], v[5], v[6],  v[7]);
    dft4(v[8], v[9], v[10], v[11]);
    dft4(v[12],v[13],v[14], v[15]);
}

// In-place (register-staged) 3072-point complex FFT over shared float2.
// Stages: radix-12 (s=1), radix-16 (s=12), radix-16 (s=192). Natural order out.
__device__ void fft3072(float2 *Z, int tid){
    float2 v[16];

    // ---- stage 1: radix-12, 256 butterflies, one per thread
    {
        int p = tid;
        #pragma unroll
        for (int i = 0; i < 12; i++) v[i] = Z[PHY(p + 256*i)];
        __syncthreads();
        dft12(v);
        #pragma unroll
        for (int k = 0; k < 12; k++){
            float2 X = v[(k/3) + 4*(k%3)];
            if (k) X = cmul(X, g_tw[p*k]);
            Z[PHY(12*p + k)] = X;
        }
        __syncthreads();
    }

    // ---- stage 2: radix-16, s=12, 192 butterflies (tid = 12*p + q)
    {
        bool act = tid < 192;
        int q = tid % 12, p = tid / 12;
        if (act){
            #pragma unroll
            for (int i = 0; i < 16; i++) v[i] = Z[PHY(tid + 192*i)];
        }
        __syncthreads();
        if (act){
            dft16(v);
            #pragma unroll
            for (int k = 0; k < 16; k++){
                float2 X = v[(k>>2) + 4*(k&3)];
                if (k && p) X = cmul(X, g_tw[12*p*k]);   // w256^{pk}
                Z[PHY(q + 192*p + 12*k)] = X;
            }
        }
        __syncthreads();
    }

    // ---- stage 3: radix-16, s=192, no twiddle
    {
        bool act = tid < 192;
        if (act){
            #pragma unroll
            for (int i = 0; i < 16; i++) v[i] = Z[PHY(tid + 192*i)];
        }
        __syncthreads();
        if (act){
            dft16(v);
            #pragma unroll
            for (int k = 0; k < 16; k++){
                float2 X = v[(k>>2) + 4*(k&3)];
                Z[PHY(tid + 192*k)] = X;
            }
        }
        __syncthreads();
    }
}

// ---------------------------------------------------------------- kernels
__global__ void init_tables(){
    int j = blockIdx.x*blockDim.x + threadIdx.x;
    if (j < WIN){
        float s, c;
        sincospif(-2.0f * (float)j / (float)WIN, &s, &c);
        g_tw[j] = make_float2(c, s);
        float sh = sinpif((float)j / (float)(WIN-1));
        g_hann[j] = sh * sh;   // 0.5 - 0.5*cos(2*pi*j/(N-1)) = sin^2(pi*j/(N-1))
    }
}

// One block = one PAIR of frames (2t, 2t+1) packed as z = x + i*y.
__global__ void __launch_bounds__(NTHREADS)
synth_kernel(const float* __restrict__ fb, const float* __restrict__ noise){
    __shared__ float2 Z[SBUF];
    __shared__ float gsx[NF];
    __shared__ float gsy[NF];

    int tp  = blockIdx.x;          // 0..499
    int b   = blockIdx.y;
    int tid = threadIdx.x;
    int t0  = 2*tp;

    // filter gains for frames t0, t0+1
    if (tid < NF){
        const float* fp = fb + (b*NF + tid)*NT + t0;
        gsx[tid] = fp[0];
        gsy[tid] = fp[1];
    }

    // load both frames: Z[n] = x[n] + i*y[n]
    int base = t0*HOP - HALF;
    const float* nb = noise + b*NOISE_LEN;
    for (int n = tid; n < WIN; n += NTHREADS){
        int i0 = base + n;
        int i1 = i0 + HOP;
        float x = (i0 >= 0 && i0 < NOISE_LEN) ? nb[i0] : 0.0f;
        float y = (i1 >= 0 && i1 < NOISE_LEN) ? nb[i1] : 0.0f;
        Z[PHY(n)] = make_float2(x, y);
    }
    __syncthreads();

    // forward FFT of packed pair
    fft3072(Z, tid);

    // Spectral separation + real filter + conjugate (inverse-via-forward).
    //   X[k] = (Z[k] + conj(Z[N-k]))/2,  Y[k] = -i*(Z[k] - conj(Z[N-k]))/2
    //   W[k]   = Hx[k]*X[k] + i*Hy[k]*Y[k]
    //   W[N-k] = Hx[k]*conj(X[k]) + i*Hy[k]*conj(Y[k])
    // store conj(W) so a forward FFT realizes the inverse.
    for (int k = tid + 1; k < HALF; k += NTHREADS){
        float2 A = Z[PHY(k)];
        float2 B = Z[PHY(WIN - k)];
        float Xx = 0.5f*(A.x + B.x), Xy = 0.5f*(A.y - B.y);
        float Yx = 0.5f*(A.y + B.y), Yy = -0.5f*(A.x - B.x);
        int band = (k - 1)/12;
        float hx = gsx[band], hy = gsy[band];
        // W[k]
        float Wx  = hx*Xx - hy*Yy;
        float Wy  = hx*Xy + hy*Yx;
        // W[N-k]
        float Vx  = hx*Xx + hy*Yy;
        float Vy  = -hx*Xy + hy*Yx;
        Z[PHY(k)]       = make_float2(Wx, -Wy);
        Z[PHY(WIN - k)] = make_float2(Vx, -Vy);
    }
    if (tid == 0){
        Z[PHY(0)] = make_float2(0.0f, 0.0f);      // H[0] = 0
        float2 A = Z[PHY(HALF)];                  // Nyquist: X=Re, Y=Im (real)
        Z[PHY(HALF)] = make_float2(gsx[NF-1]*A.x, -gsy[NF-1]*A.y);
    }
    __syncthreads();

    // forward FFT realizes inverse:  ifft(W) = conj(fft(conj(W)))/N
    fft3072(Z, tid);

    // window + store both frames:  x_f = Re(u)/N,  y_f = -Im(u)/N
    const float inv = 1.0f/(float)WIN;
    float* scx = g_scratch + (b*NT + t0)*WIN;
    float* scy = scx + WIN;
    for (int n = tid; n < WIN; n += NTHREADS){
        float2 u = Z[PHY(n)];
        float w = inv * g_hann[n];
        scx[n] =  u.x * w;
        scy[n] = -u.y * w;
    }
}

__global__ void ola_kernel(float* __restrict__ out){
    int gid = blockIdx.x*blockDim.x + threadIdx.x;
    if (gid >= NB*NOISE_LEN) return;
    int b  = gid / NOISE_LEN;
    int sp = gid - b*NOISE_LEN;
    int s  = sp + HALF;                           // position in padded timeline
    int t_hi = s / HOP; if (t_hi > NT-1) t_hi = NT-1;
    int t_lo = (s >= 2880) ? (s - 2880)/HOP : 0;  // ceil((s-3071)/192)
    const float* base = g_scratch + b*NT*WIN;
    float acc = 0.0f;
    for (int tt = t_lo; tt <= t_hi; tt++){
        acc += __ldg(&base[tt*WIN + (s - tt*HOP)]);
    }
    out[gid] = acc;
}

// ---------------------------------------------------------------- launch
extern "C" void kernel_launch(void* const* d_in, const int* in_sizes, int n_in,
                              void* d_out, int out_size){
    const float* fb    = (const float*)d_in[0];
    const float* noise = (const float*)d_in[1];
    if (n_in >= 2 && in_sizes[0] == NB*NOISE_LEN && in_sizes[1] == NB*NF*NT){
        const float* tmp = fb; fb = noise; noise = tmp;
    }
    float* out = (float*)d_out;

    init_tables<<<(WIN + 255)/256, 256>>>();
    dim3 grid(NT/2, NB);
    synth_kernel<<<grid, NTHREADS>>>(fb, noise);
    int n_out = NB*NOISE_LEN;
    ola_kernel<<<(n_out + 255)/256, 256>>>(out);
}